// round 2
// baseline (speedup 1.0000x reference)
#include <cuda_runtime.h>

// Problem constants: b=4, c=256, h=w=64 -> n=4096, GROUPS=8, HEADS=4, d=64
#define NTOK 4096

// Scratch (allocation-free rule: __device__ globals)
__device__ float g_qkv[(size_t)4 * 768 * 4096];   // (b, 3*c, n)  q rows pre-scaled by 1/8
__device__ float g_att[(size_t)4 * 256 * 4096];   // (b, c, n) attention output
__device__ float g_sA[1024];                      // per (b,c) normalize scale
__device__ float g_sB[1024];                      // per (b,c) normalize shift

// ---------------------------------------------------------------------------
// Kernel 1: GroupNorm statistics -> per-channel affine (xn = x*sA + sB)
// grid = 32 (b*groups), block = 256
// ---------------------------------------------------------------------------
__global__ __launch_bounds__(256) void gn_stats_kernel(
    const float* __restrict__ x, const float* __restrict__ gw,
    const float* __restrict__ gb) {
    int b = blockIdx.x >> 3, g = blockIdx.x & 7;
    const float4* xp = (const float4*)(x + (size_t)(b * 256 + g * 32) * 4096);
    float s = 0.f, s2 = 0.f;
    for (int i = threadIdx.x; i < 32768; i += 256) {  // 32 ch * 4096 / 4
        float4 v = xp[i];
        s  += v.x + v.y + v.z + v.w;
        s2 += v.x * v.x + v.y * v.y + v.z * v.z + v.w * v.w;
    }
#pragma unroll
    for (int o = 16; o; o >>= 1) {
        s  += __shfl_xor_sync(~0u, s, o);
        s2 += __shfl_xor_sync(~0u, s2, o);
    }
    __shared__ float ss[8], ss2[8], stat[2];
    int w = threadIdx.x >> 5;
    if ((threadIdx.x & 31) == 0) { ss[w] = s; ss2[w] = s2; }
    __syncthreads();
    if (threadIdx.x == 0) {
        float t = 0.f, t2 = 0.f;
        for (int k = 0; k < 8; k++) { t += ss[k]; t2 += ss2[k]; }
        float mean = t * (1.f / 131072.f);
        float var  = t2 * (1.f / 131072.f) - mean * mean;
        stat[0] = mean;
        stat[1] = rsqrtf(var + 1e-5f);
    }
    __syncthreads();
    if (threadIdx.x < 32) {
        int c = g * 32 + threadIdx.x;
        float mean = stat[0], rstd = stat[1];
        float wv = gw[c];
        g_sA[b * 256 + c] = wv * rstd;
        g_sB[b * 256 + c] = gb[c] - mean * wv * rstd;
    }
}

// ---------------------------------------------------------------------------
// Kernel 2/4: fp32 tiled GEMM  out[b,o,n] = sum_c W[o,c] * B[b,c,n] + bias[o]
// mode 0: B = x normalized on the fly (sA,sB), dst = g_qkv, q rows *= 0.125
// mode 1: B = g_att, dst = out, += residual x
// block tile 64x64, K-chunk 16, 256 threads, 4x4 per thread
// ---------------------------------------------------------------------------
__global__ __launch_bounds__(256) void gemm_kernel(
    const float* __restrict__ Bext, const float* __restrict__ W,
    const float* __restrict__ bias, const float* __restrict__ resid,
    float* __restrict__ outext, int O, int mode) {
    __shared__ __align__(16) float As[16][68];
    __shared__ __align__(16) float Bs[16][64];
    int b = blockIdx.z;
    int o0 = blockIdx.x << 6, n0 = blockIdx.y << 6;
    int tid = threadIdx.x, tx = tid & 15, ty = tid >> 4;
    const float* Bb = (mode == 0 ? Bext : g_att) + (size_t)b * 256 * 4096;
    float* dst = (mode == 0) ? g_qkv : outext;
    float acc[4][4];
#pragma unroll
    for (int ii = 0; ii < 4; ii++)
#pragma unroll
        for (int jj = 0; jj < 4; jj++) acc[ii][jj] = 0.f;

    int lo = tid >> 2, lc4 = (tid & 3) << 2;   // A tile loader coords
    int bc = tid >> 4, bj4 = (tid & 15) << 2;  // B tile loader coords

    for (int c0 = 0; c0 < 256; c0 += 16) {
        float4 w4 = *(const float4*)&W[(size_t)(o0 + lo) * 256 + c0 + lc4];
        float4 v4 = *(const float4*)&Bb[(size_t)(c0 + bc) * 4096 + n0 + bj4];
        if (mode == 0) {
            float a  = g_sA[b * 256 + c0 + bc];
            float sh = g_sB[b * 256 + c0 + bc];
            v4.x = fmaf(v4.x, a, sh); v4.y = fmaf(v4.y, a, sh);
            v4.z = fmaf(v4.z, a, sh); v4.w = fmaf(v4.w, a, sh);
        }
        As[lc4 + 0][lo] = w4.x; As[lc4 + 1][lo] = w4.y;
        As[lc4 + 2][lo] = w4.z; As[lc4 + 3][lo] = w4.w;
        *(float4*)&Bs[bc][bj4] = v4;
        __syncthreads();
#pragma unroll
        for (int kc = 0; kc < 16; kc++) {
            float4 a4 = *(float4*)&As[kc][ty << 2];
            float4 b4 = *(float4*)&Bs[kc][tx << 2];
            float av[4] = {a4.x, a4.y, a4.z, a4.w};
            float bv[4] = {b4.x, b4.y, b4.z, b4.w};
#pragma unroll
            for (int ii = 0; ii < 4; ii++)
#pragma unroll
                for (int jj = 0; jj < 4; jj++)
                    acc[ii][jj] = fmaf(av[ii], bv[jj], acc[ii][jj]);
        }
        __syncthreads();
    }
#pragma unroll
    for (int ii = 0; ii < 4; ii++) {
        int o = o0 + (ty << 2) + ii;
        float bia = bias[o];
        float4 r;
        r.x = acc[ii][0] + bia; r.y = acc[ii][1] + bia;
        r.z = acc[ii][2] + bia; r.w = acc[ii][3] + bia;
        if (mode == 0) {
            if (o < 256) {  // q rows: fold in softmax scale d^-1/2 = 1/8
                r.x *= 0.125f; r.y *= 0.125f; r.z *= 0.125f; r.w *= 0.125f;
            }
        } else {
            float4 x4 = *(const float4*)&resid[((size_t)b * 256 + o) * 4096 + n0 + (tx << 2)];
            r.x += x4.x; r.y += x4.y; r.z += x4.z; r.w += x4.w;
        }
        *(float4*)&dst[((size_t)b * O + o) * 4096 + n0 + (tx << 2)] = r;
    }
}

// ---------------------------------------------------------------------------
// Kernel 3: flash attention, fp32.
// grid = (64 query tiles, 16 batch*head), block = 256 (16x16 logical).
// Q tile 64x64 resident in SMEM; loop 64-wide K/V chunks with online softmax.
// Layouts: Qs/Ks [d][i|j] pitch 64; Vt [j][d] pitch 65; Ps [i][j] pitch 65.
// ---------------------------------------------------------------------------
__global__ __launch_bounds__(256) void flash_kernel() {
    extern __shared__ float sm[];
    float* Qs = sm;                 // 64*64
    float* Ks = Qs + 4096;          // 64*64
    float* Vt = Ks + 4096;          // 64*65 (j-major, padded)
    float* Ps = Vt + 64 * 65;       // 64*65 (i-major, padded)

    int bh = blockIdx.y;
    int b = bh >> 2, hd = bh & 3;
    int tid = threadIdx.x, tx = tid & 15, ty = tid >> 4;
    int i0 = blockIdx.x << 6;

    const float* qb = g_qkv + ((size_t)b * 768 + hd * 64) * 4096;
    const float* kb = qb + (size_t)256 * 4096;
    const float* vb = qb + (size_t)512 * 4096;

    int ld = tid >> 4, lj4 = (tid & 15) << 2;
#pragma unroll
    for (int r = 0; r < 4; r++) {
        int d = ld + (r << 4);
        *(float4*)&Qs[(d << 6) + lj4] = *(const float4*)&qb[(size_t)d * 4096 + i0 + lj4];
    }

    float m[4], l[4], acc[4][4];
#pragma unroll
    for (int ii = 0; ii < 4; ii++) {
        m[ii] = -1e30f; l[ii] = 0.f;
#pragma unroll
        for (int jj = 0; jj < 4; jj++) acc[ii][jj] = 0.f;
    }

    for (int j0 = 0; j0 < 4096; j0 += 64) {
        __syncthreads();  // protect Ks/Vt/Ps from previous chunk's readers
#pragma unroll
        for (int r = 0; r < 4; r++) {
            int d = ld + (r << 4);
            *(float4*)&Ks[(d << 6) + lj4] = *(const float4*)&kb[(size_t)d * 4096 + j0 + lj4];
            float4 v = *(const float4*)&vb[(size_t)d * 4096 + j0 + lj4];
            Vt[(lj4 + 0) * 65 + d] = v.x;
            Vt[(lj4 + 1) * 65 + d] = v.y;
            Vt[(lj4 + 2) * 65 + d] = v.z;
            Vt[(lj4 + 3) * 65 + d] = v.w;
        }
        __syncthreads();

        // S = (Q*scale)^T K
        float s[4][4];
#pragma unroll
        for (int ii = 0; ii < 4; ii++)
#pragma unroll
            for (int jj = 0; jj < 4; jj++) s[ii][jj] = 0.f;
#pragma unroll 8
        for (int d = 0; d < 64; d++) {
            float4 a4 = *(float4*)&Qs[(d << 6) + (ty << 2)];
            float4 b4 = *(float4*)&Ks[(d << 6) + (tx << 2)];
            float av[4] = {a4.x, a4.y, a4.z, a4.w};
            float bv[4] = {b4.x, b4.y, b4.z, b4.w};
#pragma unroll
            for (int ii = 0; ii < 4; ii++)
#pragma unroll
                for (int jj = 0; jj < 4; jj++)
                    s[ii][jj] = fmaf(av[ii], bv[jj], s[ii][jj]);
        }

        // online softmax per query row (row group = 16 lanes sharing ty)
#pragma unroll
        for (int ii = 0; ii < 4; ii++) {
            float mx = fmaxf(fmaxf(s[ii][0], s[ii][1]), fmaxf(s[ii][2], s[ii][3]));
#pragma unroll
            for (int o = 8; o; o >>= 1) mx = fmaxf(mx, __shfl_xor_sync(~0u, mx, o));
            float mn = fmaxf(m[ii], mx);
            float al = __expf(m[ii] - mn);
            float rs = 0.f;
#pragma unroll
            for (int jj = 0; jj < 4; jj++) {
                s[ii][jj] = __expf(s[ii][jj] - mn);
                rs += s[ii][jj];
            }
#pragma unroll
            for (int o = 8; o; o >>= 1) rs += __shfl_xor_sync(~0u, rs, o);
            l[ii] = l[ii] * al + rs;
            m[ii] = mn;
#pragma unroll
            for (int jj = 0; jj < 4; jj++) {
                acc[ii][jj] *= al;
                Ps[((ty << 2) + ii) * 65 + (tx << 2) + jj] = s[ii][jj];
            }
        }
        __syncthreads();

        // O += P @ V^T  (acc[ii][jj] : i = ty*4+ii, d = tx*4+jj)
#pragma unroll 4
        for (int j = 0; j < 64; j++) {
            float pv[4], vv[4];
#pragma unroll
            for (int ii = 0; ii < 4; ii++) pv[ii] = Ps[((ty << 2) + ii) * 65 + j];
#pragma unroll
            for (int jj = 0; jj < 4; jj++) vv[jj] = Vt[j * 65 + (tx << 2) + jj];
#pragma unroll
            for (int ii = 0; ii < 4; ii++)
#pragma unroll
                for (int jj = 0; jj < 4; jj++)
                    acc[ii][jj] = fmaf(pv[ii], vv[jj], acc[ii][jj]);
        }
    }

    float rl[4];
#pragma unroll
    for (int ii = 0; ii < 4; ii++) rl[ii] = 1.f / l[ii];
#pragma unroll
    for (int jj = 0; jj < 4; jj++) {
        int d = (tx << 2) + jj;
        float4 r;
        r.x = acc[0][jj] * rl[0];
        r.y = acc[1][jj] * rl[1];
        r.z = acc[2][jj] * rl[2];
        r.w = acc[3][jj] * rl[3];
        *(float4*)&g_att[((size_t)(b * 256) + hd * 64 + d) * 4096 + i0 + (ty << 2)] = r;
    }
}

// ---------------------------------------------------------------------------
extern "C" void kernel_launch(void* const* d_in, const int* in_sizes, int n_in,
                              void* d_out, int out_size) {
    const float* x      = (const float*)d_in[0];
    const float* gn_w   = (const float*)d_in[1];
    const float* gn_b   = (const float*)d_in[2];
    const float* qkv_w  = (const float*)d_in[3];
    const float* qkv_b  = (const float*)d_in[4];
    const float* proj_w = (const float*)d_in[5];
    const float* proj_b = (const float*)d_in[6];
    float* out = (float*)d_out;

    const int flash_smem = (4096 + 4096 + 64 * 65 + 64 * 65) * 4;  // 66048 B
    static bool attr_set = false;
    if (!attr_set) {
        cudaFuncSetAttribute(flash_kernel,
                             cudaFuncAttributeMaxDynamicSharedMemorySize, flash_smem);
        attr_set = true;
    }

    gn_stats_kernel<<<32, 256>>>(x, gn_w, gn_b);

    dim3 gq(12, 64, 4);  // 768/64 x 4096/64 x b
    gemm_kernel<<<gq, 256>>>(x, qkv_w, qkv_b, nullptr, nullptr, 768, 0);

    dim3 gf(64, 16);     // query tiles x (b*heads)
    flash_kernel<<<gf, 256, flash_smem>>>();

    dim3 gp(4, 64, 4);   // 256/64 x 4096/64 x b
    gemm_kernel<<<gp, 256>>>(nullptr, proj_w, proj_b, x, out, 256, 1);
}

// round 6
// speedup vs baseline: 2.9024x; 2.9024x over previous
#include <cuda_runtime.h>
#include <cuda_bf16.h>
#include <cstdint>

// Problem: b=4, c=256, h=w=64 -> n=4096, GROUPS=8, HEADS=4, head_dim=64
// bh = b*4+head in [0,16)

// ---------------------------------------------------------------------------
// Scratch (__device__ globals; no allocation allowed)
// ---------------------------------------------------------------------------
__device__ __nv_bfloat16 g_qh[(size_t)16 * 4096 * 64];  // [bh][n][d] hi, q pre-scaled 1/8
__device__ __nv_bfloat16 g_ql[(size_t)16 * 4096 * 64];  // [bh][n][d] lo residual
__device__ __nv_bfloat16 g_kh[(size_t)16 * 4096 * 64];  // [bh][n][d] hi
__device__ __nv_bfloat16 g_kl[(size_t)16 * 4096 * 64];  // [bh][n][d] lo
__device__ __nv_bfloat16 g_vh[(size_t)16 * 4096 * 64];  // [bh][n][d]
__device__ float g_att[(size_t)4 * 256 * 4096];         // [b][c][n]
__device__ float g_sA[1024];
__device__ float g_sB[1024];

// ---------------------------------------------------------------------------
// PTX helpers (baseline sm_80+ features only; no 'a'-suffix instructions)
// ---------------------------------------------------------------------------
__device__ __forceinline__ uint32_t smem_to_u32(const void* p) {
    uint32_t a;
    asm("{ .reg .u64 t; cvta.to.shared.u64 t, %1; cvt.u32.u64 %0, t; }" : "=r"(a) : "l"(p));
    return a;
}
#define CVT_BF16X2(res, a, b) \
    asm("cvt.rn.satfinite.bf16x2.f32 %0, %1, %2;" : "=r"(res) : "f"(b), "f"(a))
#define LDSM4(r0, r1, r2, r3, addr) \
    asm volatile("ldmatrix.sync.aligned.m8n8.x4.shared.b16 {%0,%1,%2,%3}, [%4];" \
        : "=r"(r0), "=r"(r1), "=r"(r2), "=r"(r3) : "r"(addr))
#define LDSM4T(r0, r1, r2, r3, addr) \
    asm volatile("ldmatrix.sync.aligned.m8n8.x4.trans.shared.b16 {%0,%1,%2,%3}, [%4];" \
        : "=r"(r0), "=r"(r1), "=r"(r2), "=r"(r3) : "r"(addr))
#define MMA16816(c, a0, a1, a2, a3, b0, b1) \
    asm volatile("mma.sync.aligned.m16n8k16.row.col.f32.bf16.bf16.f32 " \
        "{%0,%1,%2,%3}, {%4,%5,%6,%7}, {%8,%9}, {%0,%1,%2,%3};" \
        : "+f"((c)[0]), "+f"((c)[1]), "+f"((c)[2]), "+f"((c)[3]) \
        : "r"(a0), "r"(a1), "r"(a2), "r"(a3), "r"(b0), "r"(b1))

// ---------------------------------------------------------------------------
// Kernel 1: GroupNorm statistics -> per-(b,c) affine
// ---------------------------------------------------------------------------
__global__ __launch_bounds__(256) void gn_stats_kernel(
    const float* __restrict__ x, const float* __restrict__ gw,
    const float* __restrict__ gb) {
    int b = blockIdx.x >> 3, g = blockIdx.x & 7;
    const float4* xp = (const float4*)(x + (size_t)(b * 256 + g * 32) * 4096);
    float s = 0.f, s2 = 0.f;
    for (int i = threadIdx.x; i < 32768; i += 256) {
        float4 v = xp[i];
        s  += v.x + v.y + v.z + v.w;
        s2 += v.x * v.x + v.y * v.y + v.z * v.z + v.w * v.w;
    }
#pragma unroll
    for (int o = 16; o; o >>= 1) {
        s  += __shfl_xor_sync(~0u, s, o);
        s2 += __shfl_xor_sync(~0u, s2, o);
    }
    __shared__ float ss[8], ss2[8], stat[2];
    int w = threadIdx.x >> 5;
    if ((threadIdx.x & 31) == 0) { ss[w] = s; ss2[w] = s2; }
    __syncthreads();
    if (threadIdx.x == 0) {
        float t = 0.f, t2 = 0.f;
        for (int k = 0; k < 8; k++) { t += ss[k]; t2 += ss2[k]; }
        float mean = t * (1.f / 131072.f);
        float var  = t2 * (1.f / 131072.f) - mean * mean;
        stat[0] = mean;
        stat[1] = rsqrtf(var + 1e-5f);
    }
    __syncthreads();
    if (threadIdx.x < 32) {
        int c = g * 32 + threadIdx.x;
        float wv = gw[c];
        g_sA[b * 256 + c] = wv * stat[1];
        g_sB[b * 256 + c] = gb[c] - stat[0] * wv * stat[1];
    }
}

// ---------------------------------------------------------------------------
// Kernel 2: QKV GEMM (fused GN). Epilogue: q,k -> bf16 hi+lo [n][d]
// (q pre-scaled by 1/8), v -> bf16 [n][d].
// ---------------------------------------------------------------------------
__global__ __launch_bounds__(256) void gemm_qkv_kernel(
    const float* __restrict__ X, const float* __restrict__ W,
    const float* __restrict__ bias) {
    __shared__ __align__(16) float As[16][68];
    __shared__ __align__(16) float Bs[16][64];
    int b = blockIdx.z;
    int o0 = blockIdx.x << 6, n0 = blockIdx.y << 6;
    int tid = threadIdx.x, tx = tid & 15, ty = tid >> 4;
    const float* Bb = X + (size_t)b * 256 * 4096;
    float acc[4][4];
#pragma unroll
    for (int ii = 0; ii < 4; ii++)
#pragma unroll
        for (int jj = 0; jj < 4; jj++) acc[ii][jj] = 0.f;

    int lo = tid >> 2, lc4 = (tid & 3) << 2;
    int bc = tid >> 4, bj4 = (tid & 15) << 2;

    for (int c0 = 0; c0 < 256; c0 += 16) {
        float4 w4 = *(const float4*)&W[(size_t)(o0 + lo) * 256 + c0 + lc4];
        float4 v4 = *(const float4*)&Bb[(size_t)(c0 + bc) * 4096 + n0 + bj4];
        float a  = g_sA[b * 256 + c0 + bc];
        float sh = g_sB[b * 256 + c0 + bc];
        v4.x = fmaf(v4.x, a, sh); v4.y = fmaf(v4.y, a, sh);
        v4.z = fmaf(v4.z, a, sh); v4.w = fmaf(v4.w, a, sh);
        As[lc4 + 0][lo] = w4.x; As[lc4 + 1][lo] = w4.y;
        As[lc4 + 2][lo] = w4.z; As[lc4 + 3][lo] = w4.w;
        *(float4*)&Bs[bc][bj4] = v4;
        __syncthreads();
#pragma unroll
        for (int kc = 0; kc < 16; kc++) {
            float4 a4 = *(float4*)&As[kc][ty << 2];
            float4 b4 = *(float4*)&Bs[kc][tx << 2];
            float av[4] = {a4.x, a4.y, a4.z, a4.w};
            float bv[4] = {b4.x, b4.y, b4.z, b4.w};
#pragma unroll
            for (int ii = 0; ii < 4; ii++)
#pragma unroll
                for (int jj = 0; jj < 4; jj++)
                    acc[ii][jj] = fmaf(av[ii], bv[jj], acc[ii][jj]);
        }
        __syncthreads();
    }

    int sect = o0 >> 8;                 // 0=q 1=k 2=v
    int bh = b * 4 + ((o0 >> 6) & 3);
    float bia[4];
#pragma unroll
    for (int ii = 0; ii < 4; ii++) bia[ii] = bias[o0 + (ty << 2) + ii];

    if (sect == 2) {  // v -> [n][d] bf16
#pragma unroll
        for (int jj = 0; jj < 4; jj++) {
            int n = n0 + (tx << 2) + jj;
            float v0 = acc[0][jj] + bia[0], v1 = acc[1][jj] + bia[1];
            float v2 = acc[2][jj] + bia[2], v3 = acc[3][jj] + bia[3];
            uint32_t p0, p1;
            CVT_BF16X2(p0, v0, v1);
            CVT_BF16X2(p1, v2, v3);
            *(uint2*)&g_vh[((size_t)bh * 4096 + n) * 64 + (ty << 2)] = make_uint2(p0, p1);
        }
    } else {
        float qscale = (sect == 0) ? 0.125f : 1.0f;
        __nv_bfloat16* dh = (sect == 0) ? g_qh : g_kh;
        __nv_bfloat16* dl = (sect == 0) ? g_ql : g_kl;
#pragma unroll
        for (int jj = 0; jj < 4; jj++) {
            int n = n0 + (tx << 2) + jj;
            float v[4], lof[4];
            __nv_bfloat16 hb[4];
#pragma unroll
            for (int ii = 0; ii < 4; ii++) {
                v[ii] = (acc[ii][jj] + bia[ii]) * qscale;
                hb[ii] = __float2bfloat16(v[ii]);
                lof[ii] = v[ii] - __bfloat162float(hb[ii]);
            }
            uint32_t h0 = ((uint32_t)__bfloat16_as_ushort(hb[0])) |
                          ((uint32_t)__bfloat16_as_ushort(hb[1]) << 16);
            uint32_t h1 = ((uint32_t)__bfloat16_as_ushort(hb[2])) |
                          ((uint32_t)__bfloat16_as_ushort(hb[3]) << 16);
            uint32_t l0, l1;
            CVT_BF16X2(l0, lof[0], lof[1]);
            CVT_BF16X2(l1, lof[2], lof[3]);
            size_t base = ((size_t)bh * 4096 + n) * 64 + (ty << 2);
            *(uint2*)&dh[base] = make_uint2(h0, h1);
            *(uint2*)&dl[base] = make_uint2(l0, l1);
        }
    }
}

// ---------------------------------------------------------------------------
// Kernel 3: flash attention via warp-level mma.sync (HMMA bf16, f32 accum).
// grid (64 i-tiles, 16 bh), 128 threads = 4 warps; warp w owns rows w*16..+15.
// Per 64-key chunk: S = Qh*Kh + Qh*Kl + Ql*Kh; register online softmax;
// P fragments re-packed from S accumulators; O += P*V (ldmatrix.trans on V).
// SMEM tiles [row][64 bf16] with XOR-swizzled 16B granules.
// ---------------------------------------------------------------------------
__device__ __forceinline__ void copy_tile64(char* dst, const char* src, int tid) {
    int j = tid >> 1, g0 = (tid & 1) << 2;
    const uint4* s = (const uint4*)(src + j * 128 + g0 * 16);
#pragma unroll
    for (int r = 0; r < 4; r++) {
        int g = g0 + r;
        *(uint4*)(dst + j * 128 + ((g ^ (j & 7)) << 4)) = s[r];
    }
}

__global__ __launch_bounds__(128, 3) void flash_mma_kernel() {
    __shared__ __align__(128) char sA[8192];  // Kh (stage: Qh)
    __shared__ __align__(128) char sB[8192];  // Kl (stage: Ql)
    __shared__ __align__(128) char sV[8192];  // V
    int tid = threadIdx.x, lane = tid & 31, w = tid >> 5;
    int bh = blockIdx.y, b = bh >> 2, hd = bh & 3;
    int i0 = blockIdx.x << 6;

    uint32_t uA = smem_to_u32(sA), uB = smem_to_u32(sB), uV = smem_to_u32(sV);
    const char* qhp = (const char*)g_qh + ((size_t)bh * 4096 + i0) * 128;
    const char* qlp = (const char*)g_ql + ((size_t)bh * 4096 + i0) * 128;
    const char* khp = (const char*)g_kh + ((size_t)bh * 4096) * 128;
    const char* klp = (const char*)g_kl + ((size_t)bh * 4096) * 128;
    const char* vhp = (const char*)g_vh + ((size_t)bh * 4096) * 128;

    // ---- stage Q, load A-fragments (persist in registers) ----
    copy_tile64(sA, qhp, tid);
    copy_tile64(sB, qlp, tid);
    __syncthreads();
    uint32_t qhf[4][4], qlf[4][4];
    {
        int row = (w << 4) + (lane & 15);
        int rs = row * 128, rx = (row & 7);
#pragma unroll
        for (int ks = 0; ks < 4; ks++) {
            int gr = (ks << 1) + (lane >> 4);
            uint32_t ad = uA + rs + ((gr ^ rx) << 4);
            LDSM4(qhf[ks][0], qhf[ks][1], qhf[ks][2], qhf[ks][3], ad);
            uint32_t ad2 = uB + rs + ((gr ^ rx) << 4);
            LDSM4(qlf[ks][0], qlf[ks][1], qlf[ks][2], qlf[ks][3], ad2);
        }
    }

    float ofr[8][4];
#pragma unroll
    for (int dt = 0; dt < 8; dt++)
#pragma unroll
        for (int e = 0; e < 4; e++) ofr[dt][e] = 0.f;
    float m0 = -1e30f, m1 = -1e30f, l0 = 0.f, l1 = 0.f;

    for (int j0 = 0; j0 < 4096; j0 += 64) {
        __syncthreads();
        copy_tile64(sA, khp + (size_t)j0 * 128, tid);
        copy_tile64(sB, klp + (size_t)j0 * 128, tid);
        copy_tile64(sV, vhp + (size_t)j0 * 128, tid);
        __syncthreads();

        // ---- S = Q K^T (split-bf16, 3 MMA passes) ----
        float sfr[8][4];
#pragma unroll
        for (int t = 0; t < 8; t++)
#pragma unroll
            for (int e = 0; e < 4; e++) sfr[t][e] = 0.f;

#pragma unroll
        for (int jg = 0; jg < 4; jg++) {
            int jrow = (jg << 4) + ((lane >> 4) << 3) + (lane & 7);
            int jrs = jrow * 128, jrx = (jrow & 7);
#pragma unroll
            for (int ks = 0; ks < 4; ks++) {
                int gr = (ks << 1) + ((lane >> 3) & 1);
                uint32_t off = ((gr ^ jrx) << 4);
                uint32_t k0, k1, k2, k3, e0, e1, e2, e3;
                LDSM4(k0, k1, k2, k3, uA + jrs + off);
                LDSM4(e0, e1, e2, e3, uB + jrs + off);
                MMA16816(sfr[jg * 2],     qhf[ks][0], qhf[ks][1], qhf[ks][2], qhf[ks][3], k0, k1);
                MMA16816(sfr[jg * 2 + 1], qhf[ks][0], qhf[ks][1], qhf[ks][2], qhf[ks][3], k2, k3);
                MMA16816(sfr[jg * 2],     qhf[ks][0], qhf[ks][1], qhf[ks][2], qhf[ks][3], e0, e1);
                MMA16816(sfr[jg * 2 + 1], qhf[ks][0], qhf[ks][1], qhf[ks][2], qhf[ks][3], e2, e3);
                MMA16816(sfr[jg * 2],     qlf[ks][0], qlf[ks][1], qlf[ks][2], qlf[ks][3], k0, k1);
                MMA16816(sfr[jg * 2 + 1], qlf[ks][0], qlf[ks][1], qlf[ks][2], qlf[ks][3], k2, k3);
            }
        }

        // ---- online softmax (rows r = lane>>2 and r+8) ----
        float mx0 = -1e30f, mx1 = -1e30f;
#pragma unroll
        for (int t = 0; t < 8; t++) {
            mx0 = fmaxf(mx0, fmaxf(sfr[t][0], sfr[t][1]));
            mx1 = fmaxf(mx1, fmaxf(sfr[t][2], sfr[t][3]));
        }
        mx0 = fmaxf(mx0, __shfl_xor_sync(~0u, mx0, 1));
        mx0 = fmaxf(mx0, __shfl_xor_sync(~0u, mx0, 2));
        mx1 = fmaxf(mx1, __shfl_xor_sync(~0u, mx1, 1));
        mx1 = fmaxf(mx1, __shfl_xor_sync(~0u, mx1, 2));
        float mn0 = fmaxf(m0, mx0), mn1 = fmaxf(m1, mx1);
        float al0 = __expf(m0 - mn0), al1 = __expf(m1 - mn1);
        m0 = mn0; m1 = mn1;

        float rs0 = 0.f, rs1 = 0.f;
        uint32_t p[4][4];
#pragma unroll
        for (int t = 0; t < 8; t++) {
            float e0 = __expf(sfr[t][0] - mn0), e1 = __expf(sfr[t][1] - mn0);
            float e2 = __expf(sfr[t][2] - mn1), e3 = __expf(sfr[t][3] - mn1);
            rs0 += e0 + e1; rs1 += e2 + e3;
            int ks = t >> 1, h = (t & 1) << 1;
            CVT_BF16X2(p[ks][h],     e0, e1);
            CVT_BF16X2(p[ks][h + 1], e2, e3);
        }
        rs0 += __shfl_xor_sync(~0u, rs0, 1);
        rs0 += __shfl_xor_sync(~0u, rs0, 2);
        rs1 += __shfl_xor_sync(~0u, rs1, 1);
        rs1 += __shfl_xor_sync(~0u, rs1, 2);
        l0 = l0 * al0 + rs0;
        l1 = l1 * al1 + rs1;
#pragma unroll
        for (int dt = 0; dt < 8; dt++) {
            ofr[dt][0] *= al0; ofr[dt][1] *= al0;
            ofr[dt][2] *= al1; ofr[dt][3] *= al1;
        }

        // ---- O += P V ----
#pragma unroll
        for (int ks = 0; ks < 4; ks++) {
            int jrow = (ks << 4) + (lane & 7) + (((lane >> 3) & 1) << 3);
            int jrs = jrow * 128, jrx = (jrow & 7);
            uint32_t vf[4][4];
#pragma unroll
            for (int pd = 0; pd < 4; pd++) {
                int gr = (pd << 1) + (lane >> 4);
                LDSM4T(vf[pd][0], vf[pd][1], vf[pd][2], vf[pd][3],
                       uV + jrs + ((gr ^ jrx) << 4));
            }
#pragma unroll
            for (int dt = 0; dt < 8; dt++) {
                int pd = dt >> 1, h = (dt & 1) << 1;
                MMA16816(ofr[dt], p[ks][0], p[ks][1], p[ks][2], p[ks][3],
                         vf[pd][h], vf[pd][h + 1]);
            }
        }
    }

    // ---- normalize + store (g_att [b][chan][n]) ----
    float inv0 = 1.f / l0, inv1 = 1.f / l1;
    int r = lane >> 2, c2 = (lane & 3) << 1;
    int nlo = i0 + (w << 4) + r;
    float* ab = g_att + ((size_t)b * 256 + hd * 64) * 4096;
#pragma unroll
    for (int dt = 0; dt < 8; dt++) {
        int d0 = (dt << 3) + c2;
        ab[(size_t)d0 * 4096 + nlo]           = ofr[dt][0] * inv0;
        ab[(size_t)(d0 + 1) * 4096 + nlo]     = ofr[dt][1] * inv0;
        ab[(size_t)d0 * 4096 + nlo + 8]       = ofr[dt][2] * inv1;
        ab[(size_t)(d0 + 1) * 4096 + nlo + 8] = ofr[dt][3] * inv1;
    }
}

// ---------------------------------------------------------------------------
// Kernel 4: proj GEMM + residual
// ---------------------------------------------------------------------------
__global__ __launch_bounds__(256) void gemm_proj_kernel(
    const float* __restrict__ W, const float* __restrict__ bias,
    const float* __restrict__ resid, float* __restrict__ out) {
    __shared__ __align__(16) float As[16][68];
    __shared__ __align__(16) float Bs[16][64];
    int b = blockIdx.z;
    int o0 = blockIdx.x << 6, n0 = blockIdx.y << 6;
    int tid = threadIdx.x, tx = tid & 15, ty = tid >> 4;
    const float* Bb = g_att + (size_t)b * 256 * 4096;
    float acc[4][4];
#pragma unroll
    for (int ii = 0; ii < 4; ii++)
#pragma unroll
        for (int jj = 0; jj < 4; jj++) acc[ii][jj] = 0.f;

    int lo = tid >> 2, lc4 = (tid & 3) << 2;
    int bc = tid >> 4, bj4 = (tid & 15) << 2;

    for (int c0 = 0; c0 < 256; c0 += 16) {
        float4 w4 = *(const float4*)&W[(size_t)(o0 + lo) * 256 + c0 + lc4];
        float4 v4 = *(const float4*)&Bb[(size_t)(c0 + bc) * 4096 + n0 + bj4];
        As[lc4 + 0][lo] = w4.x; As[lc4 + 1][lo] = w4.y;
        As[lc4 + 2][lo] = w4.z; As[lc4 + 3][lo] = w4.w;
        *(float4*)&Bs[bc][bj4] = v4;
        __syncthreads();
#pragma unroll
        for (int kc = 0; kc < 16; kc++) {
            float4 a4 = *(float4*)&As[kc][ty << 2];
            float4 b4 = *(float4*)&Bs[kc][tx << 2];
            float av[4] = {a4.x, a4.y, a4.z, a4.w};
            float bv[4] = {b4.x, b4.y, b4.z, b4.w};
#pragma unroll
            for (int ii = 0; ii < 4; ii++)
#pragma unroll
                for (int jj = 0; jj < 4; jj++)
                    acc[ii][jj] = fmaf(av[ii], bv[jj], acc[ii][jj]);
        }
        __syncthreads();
    }
#pragma unroll
    for (int ii = 0; ii < 4; ii++) {
        int o = o0 + (ty << 2) + ii;
        float bia = bias[o];
        float4 r;
        r.x = acc[ii][0] + bia; r.y = acc[ii][1] + bia;
        r.z = acc[ii][2] + bia; r.w = acc[ii][3] + bia;
        float4 x4 = *(const float4*)&resid[((size_t)b * 256 + o) * 4096 + n0 + (tx << 2)];
        r.x += x4.x; r.y += x4.y; r.z += x4.z; r.w += x4.w;
        *(float4*)&out[((size_t)b * 256 + o) * 4096 + n0 + (tx << 2)] = r;
    }
}

// ---------------------------------------------------------------------------
extern "C" void kernel_launch(void* const* d_in, const int* in_sizes, int n_in,
                              void* d_out, int out_size) {
    const float* x      = (const float*)d_in[0];
    const float* gn_w   = (const float*)d_in[1];
    const float* gn_b   = (const float*)d_in[2];
    const float* qkv_w  = (const float*)d_in[3];
    const float* qkv_b  = (const float*)d_in[4];
    const float* proj_w = (const float*)d_in[5];
    const float* proj_b = (const float*)d_in[6];
    float* out = (float*)d_out;

    gn_stats_kernel<<<32, 256>>>(x, gn_w, gn_b);

    dim3 gq(12, 64, 4);
    gemm_qkv_kernel<<<gq, 256>>>(x, qkv_w, qkv_b);

    dim3 gf(64, 16);
    flash_mma_kernel<<<gf, 128>>>();

    dim3 gp(4, 64, 4);
    gemm_proj_kernel<<<gp, 256>>>(proj_w, proj_b, x, out);
}

// round 7
// speedup vs baseline: 4.1050x; 1.4143x over previous
#include <cuda_runtime.h>
#include <cuda_fp16.h>
#include <cstdint>

// Problem: b=4, c=256, h=w=64 -> n=4096, GROUPS=8, HEADS=4, head_dim=64
// bh = b*4+head in [0,16)

// ---------------------------------------------------------------------------
// Scratch (__device__ globals; no allocation allowed)
// ---------------------------------------------------------------------------
__device__ __half g_q[(size_t)16 * 4096 * 64];  // [bh][n][d], pre-scaled 0.125*log2e
__device__ __half g_k[(size_t)16 * 4096 * 64];  // [bh][n][d]
__device__ __half g_v[(size_t)16 * 4096 * 64];  // [bh][n][d]
__device__ float g_att[(size_t)4 * 256 * 4096]; // [b][c][n]
__device__ float g_sA[1024];
__device__ float g_sB[1024];

// ---------------------------------------------------------------------------
// PTX helpers (baseline sm_80+ features only)
// ---------------------------------------------------------------------------
__device__ __forceinline__ uint32_t smem_to_u32(const void* p) {
    uint32_t a;
    asm("{ .reg .u64 t; cvta.to.shared.u64 t, %1; cvt.u32.u64 %0, t; }" : "=r"(a) : "l"(p));
    return a;
}
#define LDSM4(r0, r1, r2, r3, addr) \
    asm volatile("ldmatrix.sync.aligned.m8n8.x4.shared.b16 {%0,%1,%2,%3}, [%4];" \
        : "=r"(r0), "=r"(r1), "=r"(r2), "=r"(r3) : "r"(addr))
#define LDSM4T(r0, r1, r2, r3, addr) \
    asm volatile("ldmatrix.sync.aligned.m8n8.x4.trans.shared.b16 {%0,%1,%2,%3}, [%4];" \
        : "=r"(r0), "=r"(r1), "=r"(r2), "=r"(r3) : "r"(addr))
#define MMAF16(c, a0, a1, a2, a3, b0, b1) \
    asm volatile("mma.sync.aligned.m16n8k16.row.col.f32.f16.f16.f32 " \
        "{%0,%1,%2,%3}, {%4,%5,%6,%7}, {%8,%9}, {%0,%1,%2,%3};" \
        : "+f"((c)[0]), "+f"((c)[1]), "+f"((c)[2]), "+f"((c)[3]) \
        : "r"(a0), "r"(a1), "r"(a2), "r"(a3), "r"(b0), "r"(b1))
#define CP_COMMIT() asm volatile("cp.async.commit_group;" ::: "memory")
#define CP_WAIT(n)  asm volatile("cp.async.wait_group %0;" :: "n"(n) : "memory")

__device__ __forceinline__ uint32_t packh2(float a, float b) {
    __half2 h = __floats2half2_rn(a, b);
    return *(uint32_t*)&h;
}

// ---------------------------------------------------------------------------
// Kernel 1: GroupNorm statistics -> per-(b,c) affine
// ---------------------------------------------------------------------------
__global__ __launch_bounds__(256) void gn_stats_kernel(
    const float* __restrict__ x, const float* __restrict__ gw,
    const float* __restrict__ gb) {
    int b = blockIdx.x >> 3, g = blockIdx.x & 7;
    const float4* xp = (const float4*)(x + (size_t)(b * 256 + g * 32) * 4096);
    float s = 0.f, s2 = 0.f;
    for (int i = threadIdx.x; i < 32768; i += 256) {
        float4 v = xp[i];
        s  += v.x + v.y + v.z + v.w;
        s2 += v.x * v.x + v.y * v.y + v.z * v.z + v.w * v.w;
    }
#pragma unroll
    for (int o = 16; o; o >>= 1) {
        s  += __shfl_xor_sync(~0u, s, o);
        s2 += __shfl_xor_sync(~0u, s2, o);
    }
    __shared__ float ss[8], ss2[8], stat[2];
    int w = threadIdx.x >> 5;
    if ((threadIdx.x & 31) == 0) { ss[w] = s; ss2[w] = s2; }
    __syncthreads();
    if (threadIdx.x == 0) {
        float t = 0.f, t2 = 0.f;
        for (int k = 0; k < 8; k++) { t += ss[k]; t2 += ss2[k]; }
        float mean = t * (1.f / 131072.f);
        float var  = t2 * (1.f / 131072.f) - mean * mean;
        stat[0] = mean;
        stat[1] = rsqrtf(var + 1e-5f);
    }
    __syncthreads();
    if (threadIdx.x < 32) {
        int c = g * 32 + threadIdx.x;
        float wv = gw[c];
        g_sA[b * 256 + c] = wv * stat[1];
        g_sB[b * 256 + c] = gb[c] - stat[0] * wv * stat[1];
    }
}

// ---------------------------------------------------------------------------
// Kernel 2: QKV GEMM (fused GN). Epilogue: q,k,v -> fp16 [n][d];
// q pre-scaled by 0.125*log2(e) (softmax in exp2 domain).
// ---------------------------------------------------------------------------
__global__ __launch_bounds__(256) void gemm_qkv_kernel(
    const float* __restrict__ X, const float* __restrict__ W,
    const float* __restrict__ bias) {
    __shared__ __align__(16) float As[16][68];
    __shared__ __align__(16) float Bs[16][64];
    int b = blockIdx.z;
    int o0 = blockIdx.x << 6, n0 = blockIdx.y << 6;
    int tid = threadIdx.x, tx = tid & 15, ty = tid >> 4;
    const float* Bb = X + (size_t)b * 256 * 4096;
    float acc[4][4];
#pragma unroll
    for (int ii = 0; ii < 4; ii++)
#pragma unroll
        for (int jj = 0; jj < 4; jj++) acc[ii][jj] = 0.f;

    int lo = tid >> 2, lc4 = (tid & 3) << 2;
    int bc = tid >> 4, bj4 = (tid & 15) << 2;

    for (int c0 = 0; c0 < 256; c0 += 16) {
        float4 w4 = *(const float4*)&W[(size_t)(o0 + lo) * 256 + c0 + lc4];
        float4 v4 = *(const float4*)&Bb[(size_t)(c0 + bc) * 4096 + n0 + bj4];
        float a  = g_sA[b * 256 + c0 + bc];
        float sh = g_sB[b * 256 + c0 + bc];
        v4.x = fmaf(v4.x, a, sh); v4.y = fmaf(v4.y, a, sh);
        v4.z = fmaf(v4.z, a, sh); v4.w = fmaf(v4.w, a, sh);
        As[lc4 + 0][lo] = w4.x; As[lc4 + 1][lo] = w4.y;
        As[lc4 + 2][lo] = w4.z; As[lc4 + 3][lo] = w4.w;
        *(float4*)&Bs[bc][bj4] = v4;
        __syncthreads();
#pragma unroll
        for (int kc = 0; kc < 16; kc++) {
            float4 a4 = *(float4*)&As[kc][ty << 2];
            float4 b4 = *(float4*)&Bs[kc][tx << 2];
            float av[4] = {a4.x, a4.y, a4.z, a4.w};
            float bv[4] = {b4.x, b4.y, b4.z, b4.w};
#pragma unroll
            for (int ii = 0; ii < 4; ii++)
#pragma unroll
                for (int jj = 0; jj < 4; jj++)
                    acc[ii][jj] = fmaf(av[ii], bv[jj], acc[ii][jj]);
        }
        __syncthreads();
    }

    int sect = o0 >> 8;                 // 0=q 1=k 2=v
    int bh = b * 4 + ((o0 >> 6) & 3);
    float scale = (sect == 0) ? 0.18033688f : 1.0f;  // 0.125 * log2(e)
    __half* dst = (sect == 0) ? g_q : ((sect == 1) ? g_k : g_v);
    float bia[4];
#pragma unroll
    for (int ii = 0; ii < 4; ii++) bia[ii] = bias[o0 + (ty << 2) + ii];

#pragma unroll
    for (int jj = 0; jj < 4; jj++) {
        int n = n0 + (tx << 2) + jj;
        uint32_t p0 = packh2((acc[0][jj] + bia[0]) * scale, (acc[1][jj] + bia[1]) * scale);
        uint32_t p1 = packh2((acc[2][jj] + bia[2]) * scale, (acc[3][jj] + bia[3]) * scale);
        *(uint2*)&dst[((size_t)bh * 4096 + n) * 64 + (ty << 2)] = make_uint2(p0, p1);
    }
}

// ---------------------------------------------------------------------------
// Kernel 3: flash attention via warp mma.sync (fp16 in, f32 accum).
// grid (64 i-tiles, 16 bh), 128 threads = 4 warps; warp w owns rows w*16..+15.
// cp.async double-buffered K/V chunks (64 keys each); softmax in exp2 domain.
// SMEM tiles [row][64 fp16] with XOR-swizzled 16B granules.
// ---------------------------------------------------------------------------
__device__ __forceinline__ void cpasync_tile64(uint32_t dst, const char* src, int tid) {
    int j = tid >> 1, g0 = (tid & 1) << 2;
    const char* s = src + j * 128 + g0 * 16;
#pragma unroll
    for (int r = 0; r < 4; r++) {
        int g = g0 + r;
        uint32_t d = dst + j * 128 + ((g ^ (j & 7)) << 4);
        asm volatile("cp.async.cg.shared.global [%0], [%1], 16;" :: "r"(d), "l"(s + r * 16));
    }
}

__global__ __launch_bounds__(128, 3) void flash_mma_kernel() {
    __shared__ __align__(128) char sK[2][8192];
    __shared__ __align__(128) char sV[2][8192];
    int tid = threadIdx.x, lane = tid & 31, w = tid >> 5;
    int bh = blockIdx.y, b = bh >> 2, hd = bh & 3;
    int i0 = blockIdx.x << 6;

    uint32_t uK[2] = {smem_to_u32(sK[0]), smem_to_u32(sK[1])};
    uint32_t uV[2] = {smem_to_u32(sV[0]), smem_to_u32(sV[1])};
    const char* qp = (const char*)g_q + ((size_t)bh * 4096 + i0) * 128;
    const char* kp = (const char*)g_k + ((size_t)bh * 4096) * 128;
    const char* vp = (const char*)g_v + ((size_t)bh * 4096) * 128;

    // ---- stage Q via cp.async into sK[0], extract A-fragments ----
    cpasync_tile64(uK[0], qp, tid);
    CP_COMMIT();
    CP_WAIT(0);
    __syncthreads();
    uint32_t qf[4][4];
    {
        int row = (w << 4) + (lane & 15);
        int rs = row * 128, rx = (row & 7);
#pragma unroll
        for (int ks = 0; ks < 4; ks++) {
            int gr = (ks << 1) + (lane >> 4);
            LDSM4(qf[ks][0], qf[ks][1], qf[ks][2], qf[ks][3],
                  uK[0] + rs + ((gr ^ rx) << 4));
        }
    }
    __syncthreads();  // all reads of sK[0] done before chunk-0 prefetch

    // ---- prefetch chunk 0 ----
    cpasync_tile64(uK[0], kp, tid);
    cpasync_tile64(uV[0], vp, tid);
    CP_COMMIT();

    float ofr[8][4];
#pragma unroll
    for (int dt = 0; dt < 8; dt++)
#pragma unroll
        for (int e = 0; e < 4; e++) ofr[dt][e] = 0.f;
    float m0 = -1e30f, m1 = -1e30f, l0 = 0.f, l1 = 0.f;

    int st = 0;
    for (int j0 = 0; j0 < 4096; j0 += 64) {
        if (j0 + 64 < 4096) {
            cpasync_tile64(uK[st ^ 1], kp + (size_t)(j0 + 64) * 128, tid);
            cpasync_tile64(uV[st ^ 1], vp + (size_t)(j0 + 64) * 128, tid);
            CP_COMMIT();
            CP_WAIT(1);
        } else {
            CP_WAIT(0);
        }
        __syncthreads();

        // ---- S = Q K^T ----
        float sfr[8][4];
#pragma unroll
        for (int t = 0; t < 8; t++)
#pragma unroll
            for (int e = 0; e < 4; e++) sfr[t][e] = 0.f;

#pragma unroll
        for (int jg = 0; jg < 4; jg++) {
            int jrow = (jg << 4) + ((lane >> 4) << 3) + (lane & 7);
            int jrs = jrow * 128, jrx = (jrow & 7);
#pragma unroll
            for (int ks = 0; ks < 4; ks++) {
                int gr = (ks << 1) + ((lane >> 3) & 1);
                uint32_t k0, k1, k2, k3;
                LDSM4(k0, k1, k2, k3, uK[st] + jrs + ((gr ^ jrx) << 4));
                MMAF16(sfr[jg * 2],     qf[ks][0], qf[ks][1], qf[ks][2], qf[ks][3], k0, k1);
                MMAF16(sfr[jg * 2 + 1], qf[ks][0], qf[ks][1], qf[ks][2], qf[ks][3], k2, k3);
            }
        }

        // ---- online softmax (exp2 domain; rows r = lane>>2 and r+8) ----
        float mx0 = -1e30f, mx1 = -1e30f;
#pragma unroll
        for (int t = 0; t < 8; t++) {
            mx0 = fmaxf(mx0, fmaxf(sfr[t][0], sfr[t][1]));
            mx1 = fmaxf(mx1, fmaxf(sfr[t][2], sfr[t][3]));
        }
        mx0 = fmaxf(mx0, __shfl_xor_sync(~0u, mx0, 1));
        mx0 = fmaxf(mx0, __shfl_xor_sync(~0u, mx0, 2));
        mx1 = fmaxf(mx1, __shfl_xor_sync(~0u, mx1, 1));
        mx1 = fmaxf(mx1, __shfl_xor_sync(~0u, mx1, 2));
        float mn0 = fmaxf(m0, mx0), mn1 = fmaxf(m1, mx1);
        float al0 = exp2f(m0 - mn0), al1 = exp2f(m1 - mn1);
        m0 = mn0; m1 = mn1;

        float rs0 = 0.f, rs1 = 0.f;
        uint32_t p[4][4];
#pragma unroll
        for (int t = 0; t < 8; t++) {
            float e0 = exp2f(sfr[t][0] - mn0), e1 = exp2f(sfr[t][1] - mn0);
            float e2 = exp2f(sfr[t][2] - mn1), e3 = exp2f(sfr[t][3] - mn1);
            rs0 += e0 + e1; rs1 += e2 + e3;
            int ks = t >> 1, h = (t & 1) << 1;
            p[ks][h]     = packh2(e0, e1);
            p[ks][h + 1] = packh2(e2, e3);
        }
        rs0 += __shfl_xor_sync(~0u, rs0, 1);
        rs0 += __shfl_xor_sync(~0u, rs0, 2);
        rs1 += __shfl_xor_sync(~0u, rs1, 1);
        rs1 += __shfl_xor_sync(~0u, rs1, 2);
        l0 = l0 * al0 + rs0;
        l1 = l1 * al1 + rs1;
#pragma unroll
        for (int dt = 0; dt < 8; dt++) {
            ofr[dt][0] *= al0; ofr[dt][1] *= al0;
            ofr[dt][2] *= al1; ofr[dt][3] *= al1;
        }

        // ---- O += P V ----
#pragma unroll
        for (int ks = 0; ks < 4; ks++) {
            int jrow = (ks << 4) + (lane & 7) + (((lane >> 3) & 1) << 3);
            int jrs = jrow * 128, jrx = (jrow & 7);
            uint32_t vf[4][4];
#pragma unroll
            for (int pd = 0; pd < 4; pd++) {
                int gr = (pd << 1) + (lane >> 4);
                LDSM4T(vf[pd][0], vf[pd][1], vf[pd][2], vf[pd][3],
                       uV[st] + jrs + ((gr ^ jrx) << 4));
            }
#pragma unroll
            for (int dt = 0; dt < 8; dt++) {
                int pd = dt >> 1, h = (dt & 1) << 1;
                MMAF16(ofr[dt], p[ks][0], p[ks][1], p[ks][2], p[ks][3],
                       vf[pd][h], vf[pd][h + 1]);
            }
        }
        __syncthreads();  // all reads of stage st done before it is re-filled
        st ^= 1;
    }

    // ---- normalize + store (g_att [b][chan][n]) ----
    float inv0 = 1.f / l0, inv1 = 1.f / l1;
    int r = lane >> 2, c2 = (lane & 3) << 1;
    int nlo = i0 + (w << 4) + r;
    float* ab = g_att + ((size_t)b * 256 + hd * 64) * 4096;
#pragma unroll
    for (int dt = 0; dt < 8; dt++) {
        int d0 = (dt << 3) + c2;
        ab[(size_t)d0 * 4096 + nlo]           = ofr[dt][0] * inv0;
        ab[(size_t)(d0 + 1) * 4096 + nlo]     = ofr[dt][1] * inv0;
        ab[(size_t)d0 * 4096 + nlo + 8]       = ofr[dt][2] * inv1;
        ab[(size_t)(d0 + 1) * 4096 + nlo + 8] = ofr[dt][3] * inv1;
    }
}

// ---------------------------------------------------------------------------
// Kernel 4: proj GEMM + residual
// ---------------------------------------------------------------------------
__global__ __launch_bounds__(256) void gemm_proj_kernel(
    const float* __restrict__ W, const float* __restrict__ bias,
    const float* __restrict__ resid, float* __restrict__ out) {
    __shared__ __align__(16) float As[16][68];
    __shared__ __align__(16) float Bs[16][64];
    int b = blockIdx.z;
    int o0 = blockIdx.x << 6, n0 = blockIdx.y << 6;
    int tid = threadIdx.x, tx = tid & 15, ty = tid >> 4;
    const float* Bb = g_att + (size_t)b * 256 * 4096;
    float acc[4][4];
#pragma unroll
    for (int ii = 0; ii < 4; ii++)
#pragma unroll
        for (int jj = 0; jj < 4; jj++) acc[ii][jj] = 0.f;

    int lo = tid >> 2, lc4 = (tid & 3) << 2;
    int bc = tid >> 4, bj4 = (tid & 15) << 2;

    for (int c0 = 0; c0 < 256; c0 += 16) {
        float4 w4 = *(const float4*)&W[(size_t)(o0 + lo) * 256 + c0 + lc4];
        float4 v4 = *(const float4*)&Bb[(size_t)(c0 + bc) * 4096 + n0 + bj4];
        As[lc4 + 0][lo] = w4.x; As[lc4 + 1][lo] = w4.y;
        As[lc4 + 2][lo] = w4.z; As[lc4 + 3][lo] = w4.w;
        *(float4*)&Bs[bc][bj4] = v4;
        __syncthreads();
#pragma unroll
        for (int kc = 0; kc < 16; kc++) {
            float4 a4 = *(float4*)&As[kc][ty << 2];
            float4 b4 = *(float4*)&Bs[kc][tx << 2];
            float av[4] = {a4.x, a4.y, a4.z, a4.w};
            float bv[4] = {b4.x, b4.y, b4.z, b4.w};
#pragma unroll
            for (int ii = 0; ii < 4; ii++)
#pragma unroll
                for (int jj = 0; jj < 4; jj++)
                    acc[ii][jj] = fmaf(av[ii], bv[jj], acc[ii][jj]);
        }
        __syncthreads();
    }
#pragma unroll
    for (int ii = 0; ii < 4; ii++) {
        int o = o0 + (ty << 2) + ii;
        float bia = bias[o];
        float4 r;
        r.x = acc[ii][0] + bia; r.y = acc[ii][1] + bia;
        r.z = acc[ii][2] + bia; r.w = acc[ii][3] + bia;
        float4 x4 = *(const float4*)&resid[((size_t)b * 256 + o) * 4096 + n0 + (tx << 2)];
        r.x += x4.x; r.y += x4.y; r.z += x4.z; r.w += x4.w;
        *(float4*)&out[((size_t)b * 256 + o) * 4096 + n0 + (tx << 2)] = r;
    }
}

// ---------------------------------------------------------------------------
extern "C" void kernel_launch(void* const* d_in, const int* in_sizes, int n_in,
                              void* d_out, int out_size) {
    const float* x      = (const float*)d_in[0];
    const float* gn_w   = (const float*)d_in[1];
    const float* gn_b   = (const float*)d_in[2];
    const float* qkv_w  = (const float*)d_in[3];
    const float* qkv_b  = (const float*)d_in[4];
    const float* proj_w = (const float*)d_in[5];
    const float* proj_b = (const float*)d_in[6];
    float* out = (float*)d_out;

    gn_stats_kernel<<<32, 256>>>(x, gn_w, gn_b);

    dim3 gq(12, 64, 4);
    gemm_qkv_kernel<<<gq, 256>>>(x, qkv_w, qkv_b);

    dim3 gf(64, 16);
    flash_mma_kernel<<<gf, 128>>>();

    dim3 gp(4, 64, 4);
    gemm_proj_kernel<<<gp, 256>>>(proj_w, proj_b, x, out);
}

// round 9
// speedup vs baseline: 6.0303x; 1.4690x over previous
#include <cuda_runtime.h>
#include <cuda_fp16.h>
#include <cstdint>

// Problem: b=4, c=256, h=w=64 -> n=4096, GROUPS=8, HEADS=4, head_dim=64
// bh = b*4+head in [0,16)

// ---------------------------------------------------------------------------
// Scratch (__device__ globals; no allocation allowed)
// ---------------------------------------------------------------------------
__device__ __half g_xh[(size_t)4 * 256 * 4096];   // normalized x, fp16 [b*256+c][n]
__device__ __half g_wqh[768 * 256];               // qkv_w fp16
__device__ __half g_pwh[256 * 256];               // proj_w fp16 hi
__device__ __half g_pwl[256 * 256];               // proj_w fp16 lo
__device__ __half g_q[(size_t)16 * 4096 * 64];    // [bh][n][d], pre-scaled 0.125*log2e
__device__ __half g_k[(size_t)16 * 4096 * 64];    // [bh][n][d]
__device__ __half g_v[(size_t)16 * 4096 * 64];    // [bh][n][d]
__device__ __half g_ath[(size_t)4 * 4096 * 256];  // attention out hi [b][n][c]
__device__ __half g_atl[(size_t)4 * 4096 * 256];  // attention out lo [b][n][c]
__device__ float g_sA[1024];
__device__ float g_sB[1024];

// ---------------------------------------------------------------------------
// PTX helpers (baseline sm_80+ features only)
// ---------------------------------------------------------------------------
__device__ __forceinline__ uint32_t smem_to_u32(const void* p) {
    uint32_t a;
    asm("{ .reg .u64 t; cvta.to.shared.u64 t, %1; cvt.u32.u64 %0, t; }" : "=r"(a) : "l"(p));
    return a;
}
#define LDSM4(r0, r1, r2, r3, addr) \
    asm volatile("ldmatrix.sync.aligned.m8n8.x4.shared.b16 {%0,%1,%2,%3}, [%4];" \
        : "=r"(r0), "=r"(r1), "=r"(r2), "=r"(r3) : "r"(addr))
#define LDSM4T(r0, r1, r2, r3, addr) \
    asm volatile("ldmatrix.sync.aligned.m8n8.x4.trans.shared.b16 {%0,%1,%2,%3}, [%4];" \
        : "=r"(r0), "=r"(r1), "=r"(r2), "=r"(r3) : "r"(addr))
#define MMAF16(c, a0, a1, a2, a3, b0, b1) \
    asm volatile("mma.sync.aligned.m16n8k16.row.col.f32.f16.f16.f32 " \
        "{%0,%1,%2,%3}, {%4,%5,%6,%7}, {%8,%9}, {%0,%1,%2,%3};" \
        : "+f"((c)[0]), "+f"((c)[1]), "+f"((c)[2]), "+f"((c)[3]) \
        : "r"(a0), "r"(a1), "r"(a2), "r"(a3), "r"(b0), "r"(b1))
#define CP_COMMIT() asm volatile("cp.async.commit_group;" ::: "memory")
#define CP_WAIT(n)  asm volatile("cp.async.wait_group %0;" :: "n"(n) : "memory")

__device__ __forceinline__ uint32_t packh2(float a, float b) {
    __half2 h = __floats2half2_rn(a, b);
    return *(uint32_t*)&h;
}

// cp.async one [64 rows][128B] tile into swizzled SMEM; gmem row pitch in bytes
__device__ __forceinline__ void cpa_tile(uint32_t dst, const char* src, int pitch, int tid) {
    int j = tid >> 1, g0 = (tid & 1) << 2;
    const char* s = src + (size_t)j * pitch + g0 * 16;
#pragma unroll
    for (int r = 0; r < 4; r++) {
        int g = g0 + r;
        uint32_t d = dst + j * 128 + ((g ^ (j & 7)) << 4);
        asm volatile("cp.async.cg.shared.global [%0], [%1], 16;" :: "r"(d), "l"(s + r * 16));
    }
}

// ---------------------------------------------------------------------------
// Kernel 1: GroupNorm statistics -> per-(b,c) affine
// ---------------------------------------------------------------------------
__global__ __launch_bounds__(256) void gn_stats_kernel(
    const float* __restrict__ x, const float* __restrict__ gw,
    const float* __restrict__ gb) {
    int b = blockIdx.x >> 3, g = blockIdx.x & 7;
    const float4* xp = (const float4*)(x + (size_t)(b * 256 + g * 32) * 4096);
    float s = 0.f, s2 = 0.f;
    for (int i = threadIdx.x; i < 32768; i += 256) {
        float4 v = xp[i];
        s  += v.x + v.y + v.z + v.w;
        s2 += v.x * v.x + v.y * v.y + v.z * v.z + v.w * v.w;
    }
#pragma unroll
    for (int o = 16; o; o >>= 1) {
        s  += __shfl_xor_sync(~0u, s, o);
        s2 += __shfl_xor_sync(~0u, s2, o);
    }
    __shared__ float ss[8], ss2[8], stat[2];
    int w = threadIdx.x >> 5;
    if ((threadIdx.x & 31) == 0) { ss[w] = s; ss2[w] = s2; }
    __syncthreads();
    if (threadIdx.x == 0) {
        float t = 0.f, t2 = 0.f;
        for (int k = 0; k < 8; k++) { t += ss[k]; t2 += ss2[k]; }
        float mean = t * (1.f / 131072.f);
        float var  = t2 * (1.f / 131072.f) - mean * mean;
        stat[0] = mean;
        stat[1] = rsqrtf(var + 1e-5f);
    }
    __syncthreads();
    if (threadIdx.x < 32) {
        int c = g * 32 + threadIdx.x;
        float wv = gw[c];
        g_sA[b * 256 + c] = wv * stat[1];
        g_sB[b * 256 + c] = gb[c] - stat[0] * wv * stat[1];
    }
}

// ---------------------------------------------------------------------------
// Kernel 1b: apply GN affine, write fp16 xn [b*256+c][n]
// ---------------------------------------------------------------------------
__global__ __launch_bounds__(128) void gn_apply_kernel(const float* __restrict__ x) {
    int row = blockIdx.x;
    float a = g_sA[row], sh = g_sB[row];
    const float4* xr = (const float4*)(x + (size_t)row * 4096);
    uint2* dst = (uint2*)(g_xh + (size_t)row * 4096);
    for (int i = threadIdx.x; i < 1024; i += 128) {
        float4 v = xr[i];
        uint2 p;
        p.x = packh2(fmaf(v.x, a, sh), fmaf(v.y, a, sh));
        p.y = packh2(fmaf(v.z, a, sh), fmaf(v.w, a, sh));
        dst[i] = p;
    }
}

// ---------------------------------------------------------------------------
// Kernel 1c: weight conversion (qkv_w -> fp16; proj_w -> fp16 hi+lo)
// ---------------------------------------------------------------------------
__global__ __launch_bounds__(256) void wconv_kernel(
    const float* __restrict__ qkv_w, const float* __restrict__ proj_w) {
    int i = blockIdx.x * 256 + threadIdx.x;
    if (i < 196608) g_wqh[i] = __float2half_rn(qkv_w[i]);
    int j = i - 196608;
    if (j >= 0 && j < 65536) {
        float v = proj_w[j];
        __half h = __float2half_rn(v);
        g_pwh[j] = h;
        g_pwl[j] = __float2half_rn(v - __half2float(h));
    }
}

// ---------------------------------------------------------------------------
// Kernel 2: QKV GEMM via HMMA (single-pass fp16).
// out[n 64][o 64] per CTA; A = xn^T (ldmatrix.trans on [c][n] tiles),
// B = qkv_w [o][c]. Epilogue: bias + (q scale) -> fp16 [bh][n][d].
// grid (12 o-tiles, 64 n-tiles, 4 b), 128 threads = 4 warps (warp: 16 n rows).
// ---------------------------------------------------------------------------
__global__ __launch_bounds__(128) void gemm_qkv_hmma(const float* __restrict__ bias) {
    __shared__ __align__(128) char sX[8192];  // [64 c][64 n] fp16 swizzled
    __shared__ __align__(128) char sW[8192];  // [64 o][64 c] fp16 swizzled
    int tid = threadIdx.x, lane = tid & 31, w = tid >> 5;
    int b = blockIdx.z, o0 = blockIdx.x << 6, n0 = blockIdx.y << 6;
    uint32_t uX = smem_to_u32(sX), uW = smem_to_u32(sW);

    float cfr[8][4];
#pragma unroll
    for (int t = 0; t < 8; t++)
#pragma unroll
        for (int e = 0; e < 4; e++) cfr[t][e] = 0.f;

    for (int c0 = 0; c0 < 256; c0 += 64) {
        cpa_tile(uX, (const char*)g_xh + (((size_t)(b * 256 + c0)) * 4096 + n0) * 2, 8192, tid);
        cpa_tile(uW, (const char*)g_wqh + ((size_t)o0 * 256 + c0) * 2, 512, tid);
        CP_COMMIT();
        CP_WAIT(0);
        __syncthreads();

        // A fragments (rows = n, K = c) via trans loads
        uint32_t af[4][4];
#pragma unroll
        for (int ks = 0; ks < 4; ks++) {
            int crow = (ks << 4) + ((lane >> 4) << 3) + (lane & 7);
            int g = (w << 1) + ((lane >> 3) & 1);
            LDSM4T(af[ks][0], af[ks][1], af[ks][2], af[ks][3],
                   uX + crow * 128 + ((g ^ (crow & 7)) << 4));
        }
        // B fragments + MMA
#pragma unroll
        for (int jo = 0; jo < 4; jo++) {
            int orow = (jo << 4) + ((lane >> 4) << 3) + (lane & 7);
            int ors = orow * 128, orx = orow & 7;
#pragma unroll
            for (int ks = 0; ks < 4; ks++) {
                int gr = (ks << 1) + ((lane >> 3) & 1);
                uint32_t b0, b1, b2, b3;
                LDSM4(b0, b1, b2, b3, uW + ors + ((gr ^ orx) << 4));
                MMAF16(cfr[jo * 2],     af[ks][0], af[ks][1], af[ks][2], af[ks][3], b0, b1);
                MMAF16(cfr[jo * 2 + 1], af[ks][0], af[ks][1], af[ks][2], af[ks][3], b2, b3);
            }
        }
        __syncthreads();
    }

    // epilogue: o tile = one head of one section
    int sect = o0 >> 8;                 // 0=q 1=k 2=v
    int bh = b * 4 + ((o0 >> 6) & 3);
    float scale = (sect == 0) ? 0.18033688f : 1.0f;  // 0.125 * log2(e)
    __half* dst = (sect == 0) ? g_q : ((sect == 1) ? g_k : g_v);
    int r = (w << 4) + (lane >> 2), cx = (lane & 3) << 1;
    size_t rowA = ((size_t)bh * 4096 + n0 + r) * 64;
    size_t rowB = rowA + 8 * 64;
#pragma unroll
    for (int jo = 0; jo < 4; jo++)
#pragma unroll
        for (int blk = 0; blk < 2; blk++) {
            int t = jo * 2 + blk;
            int d0 = (jo << 4) + (blk << 3) + cx;
            float b0f = bias[o0 + d0], b1f = bias[o0 + d0 + 1];
            *(uint32_t*)&dst[rowA + d0] =
                packh2((cfr[t][0] + b0f) * scale, (cfr[t][1] + b1f) * scale);
            *(uint32_t*)&dst[rowB + d0] =
                packh2((cfr[t][2] + b0f) * scale, (cfr[t][3] + b1f) * scale);
        }
}

// ---------------------------------------------------------------------------
// Kernel 3: flash attention via warp mma.sync (fp16 in, f32 accum).
// grid (64 i-tiles, 16 bh), 128 threads = 4 warps; warp w owns rows w*16..+15.
// cp.async double-buffered K/V chunks; softmax in exp2 domain.
// Output: fp16 hi+lo att [b][n][256].
// ---------------------------------------------------------------------------
__global__ __launch_bounds__(128, 3) void flash_mma_kernel() {
    __shared__ __align__(128) char sK[2][8192];
    __shared__ __align__(128) char sV[2][8192];
    int tid = threadIdx.x, lane = tid & 31, w = tid >> 5;
    int bh = blockIdx.y, b = bh >> 2, hd = bh & 3;
    int i0 = blockIdx.x << 6;

    uint32_t uK[2] = {smem_to_u32(sK[0]), smem_to_u32(sK[1])};
    uint32_t uV[2] = {smem_to_u32(sV[0]), smem_to_u32(sV[1])};
    const char* qp = (const char*)g_q + ((size_t)bh * 4096 + i0) * 128;
    const char* kp = (const char*)g_k + ((size_t)bh * 4096) * 128;
    const char* vp = (const char*)g_v + ((size_t)bh * 4096) * 128;

    cpa_tile(uK[0], qp, 128, tid);
    CP_COMMIT();
    CP_WAIT(0);
    __syncthreads();
    uint32_t qf[4][4];
    {
        int row = (w << 4) + (lane & 15);
        int rs = row * 128, rx = (row & 7);
#pragma unroll
        for (int ks = 0; ks < 4; ks++) {
            int gr = (ks << 1) + (lane >> 4);
            LDSM4(qf[ks][0], qf[ks][1], qf[ks][2], qf[ks][3],
                  uK[0] + rs + ((gr ^ rx) << 4));
        }
    }
    __syncthreads();

    cpa_tile(uK[0], kp, 128, tid);
    cpa_tile(uV[0], vp, 128, tid);
    CP_COMMIT();

    float ofr[8][4];
#pragma unroll
    for (int dt = 0; dt < 8; dt++)
#pragma unroll
        for (int e = 0; e < 4; e++) ofr[dt][e] = 0.f;
    float m0 = -1e30f, m1 = -1e30f, l0 = 0.f, l1 = 0.f;

    int st = 0;
    for (int j0 = 0; j0 < 4096; j0 += 64) {
        if (j0 + 64 < 4096) {
            cpa_tile(uK[st ^ 1], kp + (size_t)(j0 + 64) * 128, 128, tid);
            cpa_tile(uV[st ^ 1], vp + (size_t)(j0 + 64) * 128, 128, tid);
            CP_COMMIT();
            CP_WAIT(1);
        } else {
            CP_WAIT(0);
        }
        __syncthreads();

        float sfr[8][4];
#pragma unroll
        for (int t = 0; t < 8; t++)
#pragma unroll
            for (int e = 0; e < 4; e++) sfr[t][e] = 0.f;

#pragma unroll
        for (int jg = 0; jg < 4; jg++) {
            int jrow = (jg << 4) + ((lane >> 4) << 3) + (lane & 7);
            int jrs = jrow * 128, jrx = (jrow & 7);
#pragma unroll
            for (int ks = 0; ks < 4; ks++) {
                int gr = (ks << 1) + ((lane >> 3) & 1);
                uint32_t k0, k1, k2, k3;
                LDSM4(k0, k1, k2, k3, uK[st] + jrs + ((gr ^ jrx) << 4));
                MMAF16(sfr[jg * 2],     qf[ks][0], qf[ks][1], qf[ks][2], qf[ks][3], k0, k1);
                MMAF16(sfr[jg * 2 + 1], qf[ks][0], qf[ks][1], qf[ks][2], qf[ks][3], k2, k3);
            }
        }

        float mx0 = -1e30f, mx1 = -1e30f;
#pragma unroll
        for (int t = 0; t < 8; t++) {
            mx0 = fmaxf(mx0, fmaxf(sfr[t][0], sfr[t][1]));
            mx1 = fmaxf(mx1, fmaxf(sfr[t][2], sfr[t][3]));
        }
        mx0 = fmaxf(mx0, __shfl_xor_sync(~0u, mx0, 1));
        mx0 = fmaxf(mx0, __shfl_xor_sync(~0u, mx0, 2));
        mx1 = fmaxf(mx1, __shfl_xor_sync(~0u, mx1, 1));
        mx1 = fmaxf(mx1, __shfl_xor_sync(~0u, mx1, 2));
        float mn0 = fmaxf(m0, mx0), mn1 = fmaxf(m1, mx1);
        float al0 = exp2f(m0 - mn0), al1 = exp2f(m1 - mn1);
        m0 = mn0; m1 = mn1;

        float rs0 = 0.f, rs1 = 0.f;
        uint32_t p[4][4];
#pragma unroll
        for (int t = 0; t < 8; t++) {
            float e0 = exp2f(sfr[t][0] - mn0), e1 = exp2f(sfr[t][1] - mn0);
            float e2 = exp2f(sfr[t][2] - mn1), e3 = exp2f(sfr[t][3] - mn1);
            rs0 += e0 + e1; rs1 += e2 + e3;
            int ks = t >> 1, h = (t & 1) << 1;
            p[ks][h]     = packh2(e0, e1);
            p[ks][h + 1] = packh2(e2, e3);
        }
        rs0 += __shfl_xor_sync(~0u, rs0, 1);
        rs0 += __shfl_xor_sync(~0u, rs0, 2);
        rs1 += __shfl_xor_sync(~0u, rs1, 1);
        rs1 += __shfl_xor_sync(~0u, rs1, 2);
        l0 = l0 * al0 + rs0;
        l1 = l1 * al1 + rs1;
#pragma unroll
        for (int dt = 0; dt < 8; dt++) {
            ofr[dt][0] *= al0; ofr[dt][1] *= al0;
            ofr[dt][2] *= al1; ofr[dt][3] *= al1;
        }

#pragma unroll
        for (int ks = 0; ks < 4; ks++) {
            int jrow = (ks << 4) + (lane & 7) + (((lane >> 3) & 1) << 3);
            int jrs = jrow * 128, jrx = (jrow & 7);
            uint32_t vf[4][4];
#pragma unroll
            for (int pd = 0; pd < 4; pd++) {
                int gr = (pd << 1) + (lane >> 4);
                LDSM4T(vf[pd][0], vf[pd][1], vf[pd][2], vf[pd][3],
                       uV[st] + jrs + ((gr ^ jrx) << 4));
            }
#pragma unroll
            for (int dt = 0; dt < 8; dt++) {
                int pd = dt >> 1, h = (dt & 1) << 1;
                MMAF16(ofr[dt], p[ks][0], p[ks][1], p[ks][2], p[ks][3],
                       vf[pd][h], vf[pd][h + 1]);
            }
        }
        __syncthreads();
        st ^= 1;
    }

    // ---- normalize + store fp16 hi/lo att [b][n][256] ----
    float inv0 = 1.f / l0, inv1 = 1.f / l1;
    int r = lane >> 2, c2 = (lane & 3) << 1;
    int nlo = i0 + (w << 4) + r;
    size_t rowA = ((size_t)b * 4096 + nlo) * 256 + hd * 64;
    size_t rowB = rowA + (size_t)8 * 256;
#pragma unroll
    for (int dt = 0; dt < 8; dt++) {
        int d0 = (dt << 3) + c2;
        float v0 = ofr[dt][0] * inv0, v1 = ofr[dt][1] * inv0;
        float v2 = ofr[dt][2] * inv1, v3 = ofr[dt][3] * inv1;
        uint32_t hA = packh2(v0, v1);
        __half2 hh = *(__half2*)&hA;
        uint32_t lA = packh2(v0 - __low2float(hh), v1 - __high2float(hh));
        uint32_t hB = packh2(v2, v3);
        __half2 hh2 = *(__half2*)&hB;
        uint32_t lB = packh2(v2 - __low2float(hh2), v3 - __high2float(hh2));
        *(uint32_t*)&g_ath[rowA + d0] = hA;
        *(uint32_t*)&g_atl[rowA + d0] = lA;
        *(uint32_t*)&g_ath[rowB + d0] = hB;
        *(uint32_t*)&g_atl[rowB + d0] = lB;
    }
}

// ---------------------------------------------------------------------------
// Kernel 4: proj GEMM via split-fp16 HMMA (3 passes) + bias + residual.
// A = att hi/lo [n][c] tiles (LDSM non-trans), B = proj_w hi/lo [o][c].
// C [n][o] -> SMEM transpose -> out[b][o][n] fp32.
// grid (4 o-tiles, 64 n-tiles, 4 b), 128 threads.
// ---------------------------------------------------------------------------
__global__ __launch_bounds__(128) void gemm_proj_hmma(
    const float* __restrict__ bias, const float* __restrict__ resid,
    float* __restrict__ out) {
    __shared__ __align__(128) char smr[32768];  // stages; reused as fp32 [64][65]
    char* sAh = smr;
    char* sAl = smr + 8192;
    char* sWh = smr + 16384;
    char* sWl = smr + 24576;
    int tid = threadIdx.x, lane = tid & 31, w = tid >> 5;
    int b = blockIdx.z, o0 = blockIdx.x << 6, n0 = blockIdx.y << 6;
    uint32_t uAh = smem_to_u32(sAh), uAl = smem_to_u32(sAl);
    uint32_t uWh = smem_to_u32(sWh), uWl = smem_to_u32(sWl);

    float cfr[8][4];
#pragma unroll
    for (int t = 0; t < 8; t++)
#pragma unroll
        for (int e = 0; e < 4; e++) cfr[t][e] = 0.f;

    for (int c0 = 0; c0 < 256; c0 += 64) {
        cpa_tile(uAh, (const char*)g_ath + (((size_t)b * 4096 + n0) * 256 + c0) * 2, 512, tid);
        cpa_tile(uAl, (const char*)g_atl + (((size_t)b * 4096 + n0) * 256 + c0) * 2, 512, tid);
        cpa_tile(uWh, (const char*)g_pwh + ((size_t)o0 * 256 + c0) * 2, 512, tid);
        cpa_tile(uWl, (const char*)g_pwl + ((size_t)o0 * 256 + c0) * 2, 512, tid);
        CP_COMMIT();
        CP_WAIT(0);
        __syncthreads();

        uint32_t ah[4][4], al[4][4];
        {
            int row = (w << 4) + (lane & 15);
            int rs = row * 128, rx = row & 7;
#pragma unroll
            for (int ks = 0; ks < 4; ks++) {
                int gr = (ks << 1) + (lane >> 4);
                uint32_t off = ((gr ^ rx) << 4);
                LDSM4(ah[ks][0], ah[ks][1], ah[ks][2], ah[ks][3], uAh + rs + off);
                LDSM4(al[ks][0], al[ks][1], al[ks][2], al[ks][3], uAl + rs + off);
            }
        }
#pragma unroll
        for (int jo = 0; jo < 4; jo++) {
            int orow = (jo << 4) + ((lane >> 4) << 3) + (lane & 7);
            int ors = orow * 128, orx = orow & 7;
#pragma unroll
            for (int ks = 0; ks < 4; ks++) {
                int gr = (ks << 1) + ((lane >> 3) & 1);
                uint32_t off = ((gr ^ orx) << 4);
                uint32_t b0, b1, b2, b3, e0, e1, e2, e3;
                LDSM4(b0, b1, b2, b3, uWh + ors + off);
                LDSM4(e0, e1, e2, e3, uWl + ors + off);
                MMAF16(cfr[jo * 2],     ah[ks][0], ah[ks][1], ah[ks][2], ah[ks][3], b0, b1);
                MMAF16(cfr[jo * 2 + 1], ah[ks][0], ah[ks][1], ah[ks][2], ah[ks][3], b2, b3);
                MMAF16(cfr[jo * 2],     al[ks][0], al[ks][1], al[ks][2], al[ks][3], b0, b1);
                MMAF16(cfr[jo * 2 + 1], al[ks][0], al[ks][1], al[ks][2], al[ks][3], b2, b3);
                MMAF16(cfr[jo * 2],     ah[ks][0], ah[ks][1], ah[ks][2], ah[ks][3], e0, e1);
                MMAF16(cfr[jo * 2 + 1], ah[ks][0], ah[ks][1], ah[ks][2], ah[ks][3], e2, e3);
            }
        }
        __syncthreads();
    }

    // ---- transpose via SMEM, add bias + residual, store fp32 ----
    float (*sT)[65] = (float(*)[65])smr;  // 64*65*4 = 16640 B, fits in smr
    int r = (w << 4) + (lane >> 2), cx = (lane & 3) << 1;
#pragma unroll
    for (int jo = 0; jo < 4; jo++)
#pragma unroll
        for (int blk = 0; blk < 2; blk++) {
            int t = jo * 2 + blk;
            int d0 = (jo << 4) + (blk << 3) + cx;
            sT[r][d0]     = cfr[t][0];
            sT[r][d0 + 1] = cfr[t][1];
            sT[r + 8][d0]     = cfr[t][2];
            sT[r + 8][d0 + 1] = cfr[t][3];
        }
    __syncthreads();

    int orow = tid >> 1, nh = (tid & 1) << 5;
    int o = o0 + orow;
    float bia = bias[o];
    size_t base = ((size_t)b * 256 + o) * 4096 + n0 + nh;
#pragma unroll
    for (int i = 0; i < 32; i += 4) {
        float4 x4 = *(const float4*)&resid[base + i];
        float4 rr;
        rr.x = sT[nh + i][orow]     + bia + x4.x;
        rr.y = sT[nh + i + 1][orow] + bia + x4.y;
        rr.z = sT[nh + i + 2][orow] + bia + x4.z;
        rr.w = sT[nh + i + 3][orow] + bia + x4.w;
        *(float4*)&out[base + i] = rr;
    }
}

// ---------------------------------------------------------------------------
extern "C" void kernel_launch(void* const* d_in, const int* in_sizes, int n_in,
                              void* d_out, int out_size) {
    const float* x      = (const float*)d_in[0];
    const float* gn_w   = (const float*)d_in[1];
    const float* gn_b   = (const float*)d_in[2];
    const float* qkv_w  = (const float*)d_in[3];
    const float* qkv_b  = (const float*)d_in[4];
    const float* proj_w = (const float*)d_in[5];
    const float* proj_b = (const float*)d_in[6];
    float* out = (float*)d_out;

    gn_stats_kernel<<<32, 256>>>(x, gn_w, gn_b);
    gn_apply_kernel<<<1024, 128>>>(x);
    wconv_kernel<<<1024, 256>>>(qkv_w, proj_w);

    dim3 gq(12, 64, 4);
    gemm_qkv_hmma<<<gq, 128>>>(qkv_b);

    dim3 gf(64, 16);
    flash_mma_kernel<<<gf, 128>>>();

    dim3 gp(4, 64, 4);
    gemm_proj_hmma<<<gp, 128>>>(proj_b, x, out);
}